// round 1
// baseline (speedup 1.0000x reference)
#include <cuda_runtime.h>
#include <cuda_bf16.h>
#include <math.h>

// Problem constants
#define BB 128
#define LL 256
#define NN 8
#define FF 200
#define F3 600
#define AOUT 39
#define BOUT 10
#define BL (BB*LL)           // 32768
#define RROUNDS 2            // R-1
#define TSTEPS 2

// ------------------------- scratch (device globals) -------------------------
__device__ float g_h[BL*FF];
__device__ float g_act[BL*FF];
__device__ float g_ctx[BL*FF];
__device__ float g_gi[BL*F3];
__device__ float g_gh[BL*F3];
__device__ float g_s1[BL*FF];
__device__ float g_s2[BL*FF];
__device__ float g_t[BL*FF];
__device__ float g_molW[BB*FF];
__device__ float g_al[BL*AOUT];
__device__ float g_u1[BL*BOUT];
__device__ float g_u2[BL*BOUT];

// ------------------------- generic SGEMM: C = act(A @ W^T + bias + rowAdd) ---
// A: [M,K] row-major (lda=K), W: [N,K] rows with stride ldw, C: [M,N]
// ACT: 0 none, 1 elu, 2 relu
template<int ACT>
__global__ __launch_bounds__(256) void gemm_nt(
    const float* __restrict__ A, const float* __restrict__ W,
    const float* __restrict__ bias, float* __restrict__ C,
    int M, int N, int K, int ldw,
    const float* __restrict__ rowAdd, int rowsPerGroup)
{
    __shared__ float As[8][68];
    __shared__ float Bs[8][68];
    const int bm = blockIdx.y * 64;
    const int bn = blockIdx.x * 64;
    const int tid = threadIdx.x;
    const int tx = tid & 15, ty = tid >> 4;

    float acc[4][4];
    #pragma unroll
    for (int i = 0; i < 4; i++)
        #pragma unroll
        for (int j = 0; j < 4; j++) acc[i][j] = 0.f;

    for (int k0 = 0; k0 < K; k0 += 8) {
        #pragma unroll
        for (int it = 0; it < 2; it++) {
            int e = tid + it * 256;
            int r = e >> 3, c = e & 7;
            int m = bm + r;
            As[c][r] = (m < M) ? A[(size_t)m * K + k0 + c] : 0.f;
            int n = bn + r;
            Bs[c][r] = (n < N) ? W[(size_t)n * ldw + k0 + c] : 0.f;
        }
        __syncthreads();
        #pragma unroll
        for (int kk = 0; kk < 8; kk++) {
            float4 a4 = *(const float4*)&As[kk][ty * 4];
            float4 b4 = *(const float4*)&Bs[kk][tx * 4];
            float a[4] = {a4.x, a4.y, a4.z, a4.w};
            float b[4] = {b4.x, b4.y, b4.z, b4.w};
            #pragma unroll
            for (int i = 0; i < 4; i++)
                #pragma unroll
                for (int j = 0; j < 4; j++)
                    acc[i][j] += a[i] * b[j];
        }
        __syncthreads();
    }

    #pragma unroll
    for (int i = 0; i < 4; i++) {
        int m = bm + ty * 4 + i;
        if (m >= M) continue;
        #pragma unroll
        for (int j = 0; j < 4; j++) {
            int n = bn + tx * 4 + j;
            if (n >= N) continue;
            float v = acc[i][j];
            if (bias) v += bias[n];
            if (rowAdd) v += rowAdd[(size_t)(m / rowsPerGroup) * N + n];
            if (ACT == 1) v = (v > 0.f) ? v : expm1f(v);
            else if (ACT == 2) v = fmaxf(v, 0.f);
            C[(size_t)m * N + n] = v;
        }
    }
}

// ------------------------- mol phase init ------------------------------------
// h0[b,l,:] = softmax_l(dot(mol[b], actf[b,l])) * mol[b] + actf[b,l]
__global__ __launch_bounds__(256) void mol_pre_kernel(
    const float* __restrict__ molf, const float* __restrict__ actf,
    float* __restrict__ h0)
{
    int b = blockIdx.x;
    int tid = threadIdx.x;
    __shared__ float dots[LL];
    __shared__ float red[16];
    const float* mf = molf + (size_t)b * FF;
    int lane = tid & 31, warp = tid >> 5;

    for (int l = warp; l < LL; l += 8) {
        const float* af = actf + ((size_t)b * LL + l) * FF;
        float s = 0.f;
        for (int f = lane; f < FF; f += 32) s += mf[f] * af[f];
        #pragma unroll
        for (int o = 16; o > 0; o >>= 1) s += __shfl_xor_sync(0xffffffffu, s, o);
        if (lane == 0) dots[l] = s;
    }
    __syncthreads();

    float v = dots[tid];
    float m = v;
    #pragma unroll
    for (int o = 16; o > 0; o >>= 1) m = fmaxf(m, __shfl_xor_sync(0xffffffffu, m, o));
    if (lane == 0) red[warp] = m;
    __syncthreads();
    float mx = red[0];
    #pragma unroll
    for (int i = 1; i < 8; i++) mx = fmaxf(mx, red[i]);
    float e = expf(v - mx);
    float s = e;
    #pragma unroll
    for (int o = 16; o > 0; o >>= 1) s += __shfl_xor_sync(0xffffffffu, s, o);
    if (lane == 0) red[8 + warp] = s;
    __syncthreads();
    float tot = 0.f;
    #pragma unroll
    for (int i = 0; i < 8; i++) tot += red[8 + i];
    __syncthreads();
    dots[tid] = e / tot;
    __syncthreads();

    size_t base = (size_t)b * LL * FF;
    for (int i = tid; i < LL * FF; i += 256) {
        int l = i / FF, f = i - l * FF;
        h0[base + i] = dots[l] * mf[f] + actf[base + i];
    }
}

// ------------------------- GRU gate combine ----------------------------------
__global__ __launch_bounds__(256) void gru_combine_kernel(
    const float* __restrict__ gi, const float* __restrict__ gh,
    const float* __restrict__ hin, float* __restrict__ hout,
    float* __restrict__ actout, int total)
{
    int idx = blockIdx.x * blockDim.x + threadIdx.x;
    if (idx >= total) return;
    int m = idx / FF, f = idx - m * FF;
    size_t b3 = (size_t)m * F3;
    float ir = gi[b3 + f], iz = gi[b3 + FF + f], in_ = gi[b3 + 2 * FF + f];
    float hr = gh[b3 + f], hz = gh[b3 + FF + f], hn = gh[b3 + 2 * FF + f];
    float r = 1.f / (1.f + expf(-(ir + hr)));
    float z = 1.f / (1.f + expf(-(iz + hz)));
    float n = tanhf(in_ + r * hn);
    float h = hin[idx];
    float o = (1.f - z) * n + z * h;
    if (hout) hout[idx] = o;
    actout[idx] = fmaxf(o, 0.f);
}

// ------------------------- neighbor attention context ------------------------
// per (b,l,f): softmax over 8 neighbors, elu(sum attw * t[gathered])
__global__ __launch_bounds__(256) void attn_ctx_kernel(
    const float* __restrict__ s1, const float* __restrict__ s2,
    const float* __restrict__ tt, const int* __restrict__ deg,
    float* __restrict__ ctx)
{
    int bl = blockIdx.x;
    int b = bl >> 8;           // L = 256
    int tid = threadIdx.x;
    __shared__ int sidx[NN];
    if (tid < NN) sidx[tid] = deg[(size_t)bl * NN + tid];
    __syncthreads();
    if (tid >= FF) return;
    int f = tid;
    float s1v = s1[(size_t)bl * FF + f];
    float sc[NN];
    float mx = -3.4e38f;
    #pragma unroll
    for (int n = 0; n < NN; n++) {
        int j = sidx[n];
        float v = s1v + s2[((size_t)b * LL + j) * FF + f];
        v = (v >= 0.f) ? v : 0.01f * v;          // leaky_relu(0.01)
        if (j == LL - 1) v += -9e8f;              // softmax mask
        sc[n] = v;
        mx = fmaxf(mx, v);
    }
    float sum = 0.f;
    #pragma unroll
    for (int n = 0; n < NN; n++) { sc[n] = expf(sc[n] - mx); sum += sc[n]; }
    float inv = 1.f / sum;
    float c = 0.f;
    #pragma unroll
    for (int n = 0; n < NN; n++) {
        int j = sidx[n];
        if (j != LL - 1)
            c += sc[n] * inv * tt[((size_t)b * LL + j) * FF + f];
    }
    c = (c > 0.f) ? c : expm1f(c);                // elu
    ctx[(size_t)bl * FF + f] = c;
}

// ------------------------- decoders ------------------------------------------
__device__ __forceinline__ void seg_softmax_acc(const float* v, float* y, int lo, int hi) {
    float m = -3.4e38f;
    for (int i = lo; i < hi; i++) m = fmaxf(m, v[i]);
    float s = 0.f;
    for (int i = lo; i < hi; i++) s += expf(v[i] - m);
    float inv = 1.f / s;
    for (int i = lo; i < hi; i++) y[i] += expf(v[i] - m) * inv;
}
__device__ __forceinline__ float sigf(float x) { return 1.f / (1.f + expf(-x)); }

__global__ __launch_bounds__(256) void atom_act_kernel(
    const float* __restrict__ al, float* __restrict__ out, int rows)
{
    int m = blockIdx.x * blockDim.x + threadIdx.x;
    if (m >= rows) return;
    const float* x = al + (size_t)m * AOUT;
    float v[AOUT], y[AOUT];
    #pragma unroll
    for (int i = 0; i < AOUT; i++) { v[i] = x[i]; y[i] = 0.f; }
    seg_softmax_acc(v, y, 0, 16);
    seg_softmax_acc(v, y, 16, 22);
    seg_softmax_acc(v, y, 24, 30);
    seg_softmax_acc(v, y, 31, 36);
    y[24] += fmaxf(v[24], 0.f);
    y[30] += sigf(v[30]);
    y[36] += sigf(v[36]);
    y[37] += sigf(v[37]);
    y[38] += sigf(v[38]);
    float* o = out + (size_t)m * AOUT;
    #pragma unroll
    for (int i = 0; i < AOUT; i++) o[i] = y[i];
}

__global__ __launch_bounds__(256) void bond_act_kernel(
    const float* __restrict__ u1, const float* __restrict__ u2,
    const int* __restrict__ deg, float* __restrict__ out, int total)
{
    int id = blockIdx.x * blockDim.x + threadIdx.x;
    if (id >= total) return;                      // total = BL*NN
    int bl = id / NN;
    int b = bl >> 8;
    int j = deg[id];
    const float* a = u1 + (size_t)bl * BOUT;
    const float* c = u2 + ((size_t)b * LL + j) * BOUT;
    float v[BOUT], y[BOUT];
    #pragma unroll
    for (int k = 0; k < BOUT; k++) { v[k] = a[k] + c[k]; y[k] = 0.f; }
    seg_softmax_acc(v, y, 0, 4);
    seg_softmax_acc(v, y, 6, 10);
    y[4] += sigf(v[4]);
    y[5] += sigf(v[5]);
    float* o = out + (size_t)id * BOUT;
    #pragma unroll
    for (int k = 0; k < BOUT; k++) o[k] = y[k];
}

// ------------------------- host orchestration --------------------------------
static inline dim3 gemm_grid(int M, int N) {
    return dim3((N + 63) / 64, (M + 63) / 64);
}

extern "C" void kernel_launch(void* const* d_in, const int* in_sizes, int n_in,
                              void* d_out, int out_size)
{
    const int*   deg        = (const int*)  d_in[2];
    const float* molf       = (const float*)d_in[5];
    const float* actf       = (const float*)d_in[6];
    const float* atom_fc_w  = (const float*)d_in[7];
    const float* atom_fc_b  = (const float*)d_in[8];
    const float* bond_fc_w  = (const float*)d_in[9];
    const float* bond_fc_b  = (const float*)d_in[10];
    const float* align_w    = (const float*)d_in[11];
    const float* align_b    = (const float*)d_in[12];
    const float* attend_w   = (const float*)d_in[13];
    const float* attend_b   = (const float*)d_in[14];
    const float* gru_wih    = (const float*)d_in[15];
    const float* gru_whh    = (const float*)d_in[16];
    const float* gru_bih    = (const float*)d_in[17];
    const float* gru_bhh    = (const float*)d_in[18];
    const float* mol_al_w   = (const float*)d_in[19];
    const float* mol_al_b   = (const float*)d_in[20];
    const float* mgru_wih   = (const float*)d_in[21];
    const float* mgru_whh   = (const float*)d_in[22];
    const float* mgru_bih   = (const float*)d_in[23];
    const float* mgru_bhh   = (const float*)d_in[24];
    float* out = (float*)d_out;

    float *p_h, *p_act, *p_ctx, *p_gi, *p_gh, *p_s1, *p_s2, *p_t, *p_molW, *p_al, *p_u1, *p_u2;
    cudaGetSymbolAddress((void**)&p_h,    g_h);
    cudaGetSymbolAddress((void**)&p_act,  g_act);
    cudaGetSymbolAddress((void**)&p_ctx,  g_ctx);
    cudaGetSymbolAddress((void**)&p_gi,   g_gi);
    cudaGetSymbolAddress((void**)&p_gh,   g_gh);
    cudaGetSymbolAddress((void**)&p_s1,   g_s1);
    cudaGetSymbolAddress((void**)&p_s2,   g_s2);
    cudaGetSymbolAddress((void**)&p_t,    g_t);
    cudaGetSymbolAddress((void**)&p_molW, g_molW);
    cudaGetSymbolAddress((void**)&p_al,   g_al);
    cudaGetSymbolAddress((void**)&p_u1,   g_u1);
    cudaGetSymbolAddress((void**)&p_u2,   g_u2);

    // 1) mol phase init: g_h = git0
    mol_pre_kernel<<<BB, 256>>>(molf, actf, p_h);

    // 2) molW = mol_feature @ Wm[:, :F]^T + mol_align_b   (constant over t)
    gemm_nt<0><<<gemm_grid(BB, FF), 256>>>(molf, mol_al_w, mol_al_b, p_molW,
                                           BB, FF, FF, 2 * FF, nullptr, 1);

    // 3) T GRU steps on mol features
    for (int t = 0; t < TSTEPS; t++) {
        // ctx = elu(git @ Wm[:, F:2F]^T + molW[b])
        gemm_nt<1><<<gemm_grid(BL, FF), 256>>>(p_h, mol_al_w + FF, nullptr, p_ctx,
                                               BL, FF, FF, 2 * FF, p_molW, LL);
        gemm_nt<0><<<gemm_grid(BL, F3), 256>>>(p_ctx, mgru_wih, mgru_bih, p_gi,
                                               BL, F3, FF, FF, nullptr, 1);
        gemm_nt<0><<<gemm_grid(BL, F3), 256>>>(p_h, mgru_whh, mgru_bhh, p_gh,
                                               BL, F3, FF, FF, nullptr, 1);
        gru_combine_kernel<<<(BL * FF + 255) / 256, 256>>>(p_gi, p_gh, p_h, p_h, p_act, BL * FF);
    }

    // 4) R-1 rounds of neighbor attention + GRU
    for (int d = 0; d < RROUNDS; d++) {
        const float* aw = align_w + (size_t)d * FF * 2 * FF;
        gemm_nt<0><<<gemm_grid(BL, FF), 256>>>(p_act, aw, align_b + (size_t)d * FF, p_s1,
                                               BL, FF, FF, 2 * FF, nullptr, 1);
        gemm_nt<0><<<gemm_grid(BL, FF), 256>>>(p_act, aw + FF, nullptr, p_s2,
                                               BL, FF, FF, 2 * FF, nullptr, 1);
        gemm_nt<0><<<gemm_grid(BL, FF), 256>>>(p_act, attend_w + (size_t)d * FF * FF,
                                               attend_b + (size_t)d * FF, p_t,
                                               BL, FF, FF, FF, nullptr, 1);
        attn_ctx_kernel<<<BL, 256>>>(p_s1, p_s2, p_t, deg, p_ctx);
        gemm_nt<0><<<gemm_grid(BL, F3), 256>>>(p_ctx, gru_wih + (size_t)d * F3 * FF,
                                               gru_bih + (size_t)d * F3, p_gi,
                                               BL, F3, FF, FF, nullptr, 1);
        gemm_nt<0><<<gemm_grid(BL, F3), 256>>>(p_act, gru_whh + (size_t)d * F3 * FF,
                                               gru_bhh + (size_t)d * F3, p_gh,
                                               BL, F3, FF, FF, nullptr, 1);
        gru_combine_kernel<<<(BL * FF + 255) / 256, 256>>>(p_gi, p_gh, p_act, nullptr, p_act, BL * FF);
    }

    // 5) decode
    gemm_nt<0><<<gemm_grid(BL, AOUT), 256>>>(p_act, atom_fc_w, atom_fc_b, p_al,
                                             BL, AOUT, FF, FF, nullptr, 1);
    gemm_nt<0><<<gemm_grid(BL, BOUT), 256>>>(p_act, bond_fc_w, bond_fc_b, p_u1,
                                             BL, BOUT, FF, 2 * FF, nullptr, 1);
    gemm_nt<0><<<gemm_grid(BL, BOUT), 256>>>(p_act, bond_fc_w + FF, nullptr, p_u2,
                                             BL, BOUT, FF, 2 * FF, nullptr, 1);

    atom_act_kernel<<<(BL + 255) / 256, 256>>>(p_al, out, BL);
    bond_act_kernel<<<(BL * NN + 255) / 256, 256>>>(p_u1, p_u2, deg,
                                                    out + (size_t)BL * AOUT, BL * NN);
}